// round 4
// baseline (speedup 1.0000x reference)
#include <cuda_runtime.h>
#include <cuda_bf16.h>
#include <math.h>
#include <stdint.h>

#define L_LAYERS 250
#define N_TRACES 600
#define N_THETA  30
#define NI   249                 // interfaces (ref row 249 is zero -> dropped)
#define NCOL 18000               // N_TRACES * N_THETA
#define NP   18048               // padded R plane pitch (cols)
#define KPAD 256                 // padded K
#define TOTAL (NI * NCOL)

// bf16 hi/lo planes. __device__ globals are zero-initialized at module load.
// Pad regions (rows >= 249, cols >= 18000) are NEVER written by any kernel,
// so they remain zero across all graph replays — no re-zeroing needed.
__device__ __nv_bfloat16 g_Rhi[KPAD * NP];
__device__ __nv_bfloat16 g_Rlo[KPAD * NP];
__device__ __nv_bfloat16 g_Whi[256 * 256];
__device__ __nv_bfloat16 g_Wlo[256 * 256];

// ---------------------------------------------------------------------------
// Phase 1: exact Zoeppritz Rpp via the Aki & Richards closed form (eq. 5.39),
// homogeneously rescaled by a1*a2*b1*b2 to eliminate all reciprocals except
// the single final divide. Clipping never activates for these input ranges
// (p*a2 <= 0.836), so sin(arcsin(x)) = x, cos(arcsin(x)) = sqrt(1-x^2) exactly.
// Writes split-bf16 planes: r = hi + lo.
// ---------------------------------------------------------------------------
__global__ void zoe_phase1(const float* __restrict__ vp,
                           const float* __restrict__ vs,
                           const float* __restrict__ rho,
                           const float* __restrict__ theta) {
    __shared__ float s_sth[N_THETA], s_cth[N_THETA];
    int tid = threadIdx.x;
    if (tid < N_THETA) {
        float sv, cv;
        sincosf(theta[tid], &sv, &cv);
        s_sth[tid] = sv;
        s_cth[tid] = cv;
    }
    __syncthreads();

    int idx = blockIdx.x * blockDim.x + tid;
    if (idx >= TOTAL) return;

    int l = idx / NCOL;
    int n = idx - l * NCOL;
    int t = n / N_THETA;
    int a = n - t * N_THETA;

    float a1 = vp[l * N_TRACES + t],  a2 = vp[(l + 1) * N_TRACES + t];
    float b1 = vs[l * N_TRACES + t],  b2 = vs[(l + 1) * N_TRACES + t];
    float r1 = rho[l * N_TRACES + t], r2 = rho[(l + 1) * N_TRACES + t];

    float sth = s_sth[a], cth = s_cth[a];
    float p  = __fdividef(sth, a1);
    float p2 = p * p;

    float st2 = p * a2;
    float ct2 = sqrtf(fmaxf(1.f - st2 * st2, 0.f));
    float sp1 = p * b1;
    float cp1 = sqrtf(fmaxf(1.f - sp1 * sp1, 0.f));
    float sp2 = p * b2;
    float cp2 = sqrtf(fmaxf(1.f - sp2 * sp2, 0.f));

    float k1 = 2.f * r1 * (b1 * b1);
    float k2 = 2.f * r2 * (b2 * b2);
    float d  = k2 - k1;
    float dp2 = d * p2;

    float A = (r2 - r1) - dp2;      // a
    float B = r2 - dp2;             // b
    float C = r1 + dp2;             // c

    // scaled terms (each * a1*a2*b1*b2 consistently)
    float X = B * cth * a2;         // b*cos(th1)/a1  * a1*a2
    float Y = C * ct2 * a1;         // c*cos(th2)/a2  * a1*a2
    float E = X + Y;
    float F = fmaf(B * cp1, b2, C * cp2 * b1);          // F * b1*b2
    float Z = d * cth * cp2;                            // d*ct1/a1*cp2/b2 * a1*b2
    float Aa1b2 = A * a1 * b2;
    float G = Aa1b2 - Z;
    float H = fmaf(-d * ct2, cp1, A * a2 * b1);
    float GHp2 = G * H * p2;
    float D = fmaf(E, F, GHp2);
    float num = fmaf(X - Y, F, -(Aa1b2 + Z) * H * p2);

    float r = __fdividef(num, D);
    __nv_bfloat16 hi = __float2bfloat16(r);
    float lof = r - __bfloat162float(hi);
    g_Rhi[l * NP + n] = hi;
    g_Rlo[l * NP + n] = __float2bfloat16(lof);
}

// ---------------------------------------------------------------------------
// W split: W[l, k] (250x250 f32) -> 256x256 bf16 hi/lo planes (zero padded)
// ---------------------------------------------------------------------------
__global__ void zoe_wsplit(const float* __restrict__ W) {
    int idx = blockIdx.x * blockDim.x + threadIdx.x;
    if (idx >= 256 * 256) return;
    int r = idx >> 8, k = idx & 255;
    float v = (r < L_LAYERS && k < L_LAYERS) ? W[r * L_LAYERS + k] : 0.f;
    __nv_bfloat16 hi = __float2bfloat16(v);
    float lof = v - __bfloat162float(hi);
    g_Whi[idx] = hi;
    g_Wlo[idx] = __float2bfloat16(lof);
}

// ---------------------------------------------------------------------------
// Phase 2: out[t, l, a] = sum_k W[l, k] * R[k, n], n = t*30 + a
// Split-bf16 HMMA GEMM, M=256, N=18000(pad 18048), K=256.
// Block 128x128, 8 warps (2x4), warp 64x32, m16n8k16.
// acc += Ah*Bh + Ah*Bl + Al*Bh. 3-stage cp.async pipeline (dynamic smem).
// ---------------------------------------------------------------------------
#define APITCH 24    // bf16/row: 48B (16B-aligned)
#define BPITCH 136   // bf16/row: 272B (16B-aligned)
#define ASTRIDE (128 * APITCH)        // per-stage A plane (bf16 elems)
#define BSTRIDE (16 * BPITCH)
#define SMEM_BYTES ((3 * ASTRIDE * 2 + 3 * BSTRIDE * 2) * 2)   // 62976

__device__ __forceinline__ uint32_t smaddr(const void* p) {
    return (uint32_t)__cvta_generic_to_shared(p);
}
__device__ __forceinline__ void ldsm4(uint32_t a[4], uint32_t addr) {
    asm volatile("ldmatrix.sync.aligned.m8n8.x4.shared.b16 {%0,%1,%2,%3}, [%4];"
                 : "=r"(a[0]), "=r"(a[1]), "=r"(a[2]), "=r"(a[3]) : "r"(addr));
}
__device__ __forceinline__ void ldsm4t(uint32_t a[4], uint32_t addr) {
    asm volatile("ldmatrix.sync.aligned.m8n8.x4.trans.shared.b16 {%0,%1,%2,%3}, [%4];"
                 : "=r"(a[0]), "=r"(a[1]), "=r"(a[2]), "=r"(a[3]) : "r"(addr));
}
__device__ __forceinline__ void mma16816(float c[4], const uint32_t a[4], const uint32_t b[2]) {
    asm volatile("mma.sync.aligned.m16n8k16.row.col.f32.bf16.bf16.f32 "
                 "{%0,%1,%2,%3}, {%4,%5,%6,%7}, {%8,%9}, {%0,%1,%2,%3};"
                 : "+f"(c[0]), "+f"(c[1]), "+f"(c[2]), "+f"(c[3])
                 : "r"(a[0]), "r"(a[1]), "r"(a[2]), "r"(a[3]), "r"(b[0]), "r"(b[1]));
}
#define CP16(dst, src) \
    asm volatile("cp.async.ca.shared.global [%0], [%1], 16;" :: "r"(dst), "l"(src))
#define CP_COMMIT() asm volatile("cp.async.commit_group;")
#define CP_WAIT(n)  asm volatile("cp.async.wait_group %0;" :: "n"(n))

__global__ __launch_bounds__(256, 2)
void zoe_gemm(float* __restrict__ out) {
    extern __shared__ __nv_bfloat16 sm[];
    __nv_bfloat16* Ah = sm;
    __nv_bfloat16* Al = Ah + 3 * ASTRIDE;
    __nv_bfloat16* Bh = Al + 3 * ASTRIDE;
    __nv_bfloat16* Bl = Bh + 3 * BSTRIDE;

    int tid = threadIdx.x;
    int bm = blockIdx.y * 128;
    int bn = blockIdx.x * 128;

    // fill mappings (256 threads)
    int ar = tid >> 1;            // A row 0..127
    int ac = (tid & 1) * 8;       // A k-offset 0 or 8
    int br = tid >> 4;            // B k-row 0..15
    int bc = (tid & 15) * 8;      // B n-offset 0..120

    const __nv_bfloat16* pWhi = &g_Whi[(bm + ar) * 256 + ac];
    const __nv_bfloat16* pWlo = &g_Wlo[(bm + ar) * 256 + ac];
    const __nv_bfloat16* pRhi = &g_Rhi[(size_t)br * NP + bn + bc];
    const __nv_bfloat16* pRlo = &g_Rlo[(size_t)br * NP + bn + bc];

    uint32_t sAh = smaddr(&Ah[ar * APITCH + ac]);
    uint32_t sAl = smaddr(&Al[ar * APITCH + ac]);
    uint32_t sBh = smaddr(&Bh[br * BPITCH + bc]);
    uint32_t sBl = smaddr(&Bl[br * BPITCH + bc]);

    // warp tiling
    int wid = tid >> 5, lane = tid & 31;
    int wm = (wid >> 2) * 64;
    int wn = (wid & 3) * 32;
    int r8 = lane >> 3, i8 = lane & 7;
    int a_row = wm + (r8 & 1) * 8 + i8;
    int a_col = (r8 >> 1) * 8;
    int b_krow = (r8 & 1) * 8 + i8;
    int b_ncol = wn + (r8 >> 1) * 8;

    float acc[4][4][4];
#pragma unroll
    for (int mt = 0; mt < 4; mt++)
#pragma unroll
        for (int nt = 0; nt < 4; nt++)
#pragma unroll
            for (int e = 0; e < 4; e++) acc[mt][nt][e] = 0.f;

    const int NSTEP = KPAD / 16;  // 16

    // prologue: stages 0 and 1
#pragma unroll
    for (int s = 0; s < 2; s++) {
        int k0 = s * 16;
        CP16(sAh + s * ASTRIDE * 2, pWhi + k0);
        CP16(sAl + s * ASTRIDE * 2, pWlo + k0);
        CP16(sBh + s * BSTRIDE * 2, pRhi + (size_t)k0 * NP);
        CP16(sBl + s * BSTRIDE * 2, pRlo + (size_t)k0 * NP);
        CP_COMMIT();
    }

    for (int s = 0; s < NSTEP; s++) {
        int buf = s % 3;
        CP_WAIT(1);          // oldest outstanding group (stage s) complete
        __syncthreads();

        const __nv_bfloat16* cAh = Ah + buf * ASTRIDE;
        const __nv_bfloat16* cAl = Al + buf * ASTRIDE;
        const __nv_bfloat16* cBh = Bh + buf * BSTRIDE;
        const __nv_bfloat16* cBl = Bl + buf * BSTRIDE;

        // B fragments
        uint32_t bhf[4][2], blf[4][2];
#pragma unroll
        for (int pair = 0; pair < 2; pair++) {
            uint32_t t4[4];
            ldsm4t(t4, smaddr(&cBh[b_krow * BPITCH + b_ncol + pair * 16]));
            bhf[pair * 2][0] = t4[0]; bhf[pair * 2][1] = t4[1];
            bhf[pair * 2 + 1][0] = t4[2]; bhf[pair * 2 + 1][1] = t4[3];
            ldsm4t(t4, smaddr(&cBl[b_krow * BPITCH + b_ncol + pair * 16]));
            blf[pair * 2][0] = t4[0]; blf[pair * 2][1] = t4[1];
            blf[pair * 2 + 1][0] = t4[2]; blf[pair * 2 + 1][1] = t4[3];
        }

#pragma unroll
        for (int mt = 0; mt < 4; mt++) {
            uint32_t ahf[4], alf[4];
            ldsm4(ahf, smaddr(&cAh[(a_row + mt * 16) * APITCH + a_col]));
            ldsm4(alf, smaddr(&cAl[(a_row + mt * 16) * APITCH + a_col]));
#pragma unroll
            for (int nt = 0; nt < 4; nt++) {
                mma16816(acc[mt][nt], ahf, bhf[nt]);
                mma16816(acc[mt][nt], ahf, blf[nt]);
                mma16816(acc[mt][nt], alf, bhf[nt]);
            }
        }

        // issue stage s+2 into buffer (s+2)%3 (readers of that buffer finished
        // before the syncthreads above); always commit to keep group counting.
        if (s + 2 < NSTEP) {
            int nb = (s + 2) % 3;
            int k0 = (s + 2) * 16;
            CP16(sAh + nb * ASTRIDE * 2, pWhi + k0);
            CP16(sAl + nb * ASTRIDE * 2, pWlo + k0);
            CP16(sBh + nb * BSTRIDE * 2, pRhi + (size_t)k0 * NP);
            CP16(sBl + nb * BSTRIDE * 2, pRlo + (size_t)k0 * NP);
        }
        CP_COMMIT();
    }

    // epilogue
#pragma unroll
    for (int mt = 0; mt < 4; mt++) {
#pragma unroll
        for (int nt = 0; nt < 4; nt++) {
            int l0 = bm + wm + mt * 16 + (lane >> 2);
            int n0 = bn + wn + nt * 8 + (lane & 3) * 2;
#pragma unroll
            for (int e = 0; e < 4; e++) {
                int l = l0 + (e >> 1) * 8;
                int n = n0 + (e & 1);
                if (l < L_LAYERS && n < NCOL) {
                    int t = n / N_THETA;
                    int a = n - t * N_THETA;
                    out[t * (L_LAYERS * N_THETA) + l * N_THETA + a] = acc[mt][nt][e];
                }
            }
        }
    }
}

extern "C" void kernel_launch(void* const* d_in, const int* in_sizes, int n_in,
                              void* d_out, int out_size) {
    const float* vp      = (const float*)d_in[0];
    const float* vs      = (const float*)d_in[1];
    const float* rho     = (const float*)d_in[2];
    const float* theta   = (const float*)d_in[3];
    const float* wavemat = (const float*)d_in[4];
    float* out = (float*)d_out;

    static int smem_set = 0;
    if (!smem_set) {
        cudaFuncSetAttribute(zoe_gemm, cudaFuncAttributeMaxDynamicSharedMemorySize,
                             SMEM_BYTES);
        smem_set = 1;
    }

    zoe_wsplit<<<(256 * 256 + 255) / 256, 256>>>(wavemat);
    zoe_phase1<<<(TOTAL + 255) / 256, 256>>>(vp, vs, rho, theta);

    dim3 grid((NCOL + 127) / 128, 2);
    zoe_gemm<<<grid, 256, SMEM_BYTES>>>(out);
}

// round 5
// speedup vs baseline: 1.3625x; 1.3625x over previous
#include <cuda_runtime.h>
#include <cuda_bf16.h>
#include <math.h>
#include <stdint.h>

#define L_LAYERS 250
#define N_TRACES 600
#define N_THETA  30
#define NI   249                 // interfaces (ref row 249 is zero -> dropped)
#define NCOL 18000               // N_TRACES * N_THETA
#define NP   18048               // padded R plane pitch (cols)
#define KPAD 256                 // padded K
#define TOTAL (NI * NCOL)
#define WELEMS (256 * 256)

// bf16 hi/lo planes. __device__ globals are zero-initialized at module load.
// Pad regions (rows >= 249, cols >= 18000) are NEVER written by any kernel,
// so they remain zero across all graph replays.
__device__ __nv_bfloat16 g_Rhi[KPAD * NP];
__device__ __nv_bfloat16 g_Rlo[KPAD * NP];
__device__ __nv_bfloat16 g_Whi[256 * 256];
__device__ __nv_bfloat16 g_Wlo[256 * 256];

__device__ __forceinline__ float sqrt_approx(float x) {
    float r;
    asm("sqrt.approx.f32 %0, %1;" : "=f"(r) : "f"(x));
    return r;
}

// ---------------------------------------------------------------------------
// Phase 1 (fused): exact Zoeppritz Rpp via the Aki & Richards closed form,
// homogeneously rescaled by a1*a2*b1*b2 so the only reciprocal is the final
// divide. Clipping never activates for these input ranges (p*a2 <= 0.836).
// Writes split-bf16 planes r = hi + lo.
// Blocks past the R range perform the W fp32 -> split-bf16 conversion.
// ---------------------------------------------------------------------------
__global__ void zoe_phase1(const float* __restrict__ vp,
                           const float* __restrict__ vs,
                           const float* __restrict__ rho,
                           const float* __restrict__ theta,
                           const float* __restrict__ W) {
    int gidx = blockIdx.x * 256 + threadIdx.x;

    if (gidx >= TOTAL) {
        // ---- W split region: idx 0 .. 65535 ----
        int idx = gidx - TOTAL;
        if (idx < WELEMS) {
            int r = idx >> 8, k = idx & 255;
            float v = (r < L_LAYERS && k < L_LAYERS) ? W[r * L_LAYERS + k] : 0.f;
            __nv_bfloat16 hi = __float2bfloat16(v);
            float lof = v - __bfloat162float(hi);
            g_Whi[idx] = hi;
            g_Wlo[idx] = __float2bfloat16(lof);
        }
        return;
    }

    __shared__ float s_sth[N_THETA], s_cth[N_THETA];
    int tid = threadIdx.x;
    if (tid < N_THETA) {
        float sv, cv;
        sincosf(theta[tid], &sv, &cv);
        s_sth[tid] = sv;
        s_cth[tid] = cv;
    }
    __syncthreads();

    int l = gidx / NCOL;
    int n = gidx - l * NCOL;
    int t = n / N_THETA;
    int a = n - t * N_THETA;

    float a1 = vp[l * N_TRACES + t],  a2 = vp[(l + 1) * N_TRACES + t];
    float b1 = vs[l * N_TRACES + t],  b2 = vs[(l + 1) * N_TRACES + t];
    float r1 = rho[l * N_TRACES + t], r2 = rho[(l + 1) * N_TRACES + t];

    float sth = s_sth[a], cth = s_cth[a];
    float p  = __fdividef(sth, a1);
    float p2 = p * p;

    float st2 = p * a2;
    float ct2 = sqrt_approx(fmaxf(1.f - st2 * st2, 0.f));
    float sp1 = p * b1;
    float cp1 = sqrt_approx(fmaxf(1.f - sp1 * sp1, 0.f));
    float sp2 = p * b2;
    float cp2 = sqrt_approx(fmaxf(1.f - sp2 * sp2, 0.f));

    float k1 = 2.f * r1 * (b1 * b1);
    float k2 = 2.f * r2 * (b2 * b2);
    float d  = k2 - k1;
    float dp2 = d * p2;

    float A = (r2 - r1) - dp2;
    float B = r2 - dp2;
    float C = r1 + dp2;

    float X = B * cth * a2;
    float Y = C * ct2 * a1;
    float E = X + Y;
    float F = fmaf(B * cp1, b2, C * cp2 * b1);
    float Z = d * cth * cp2;
    float Aa1b2 = A * a1 * b2;
    float G = Aa1b2 - Z;
    float H = fmaf(-d * ct2, cp1, A * a2 * b1);
    float GHp2 = G * H * p2;
    float D = fmaf(E, F, GHp2);
    float num = fmaf(X - Y, F, -(Aa1b2 + Z) * H * p2);

    float r = __fdividef(num, D);
    __nv_bfloat16 hi = __float2bfloat16(r);
    float lof = r - __bfloat162float(hi);
    g_Rhi[l * NP + n] = hi;
    g_Rlo[l * NP + n] = __float2bfloat16(lof);
}

// ---------------------------------------------------------------------------
// Phase 2: out[t, l, a] = sum_k W[l, k] * R[k, n], n = t*30 + a
// Split-bf16 HMMA GEMM: M=256, N=18000, K=256.
// Block 128x128, 8 warps (2x4), warp 64x32, m16n8k16.
// acc += Ah*Bh + Ah*Bl + Al*Bh. 2-stage cp.async double buffering
// (proven round-3 configuration: static smem, s&1 indexing).
// ---------------------------------------------------------------------------
#define APITCH 24
#define BPITCH 136

__device__ __forceinline__ uint32_t smaddr(const void* p) {
    return (uint32_t)__cvta_generic_to_shared(p);
}
__device__ __forceinline__ void ldsm4(uint32_t a[4], uint32_t addr) {
    asm volatile("ldmatrix.sync.aligned.m8n8.x4.shared.b16 {%0,%1,%2,%3}, [%4];"
                 : "=r"(a[0]), "=r"(a[1]), "=r"(a[2]), "=r"(a[3]) : "r"(addr));
}
__device__ __forceinline__ void ldsm4t(uint32_t a[4], uint32_t addr) {
    asm volatile("ldmatrix.sync.aligned.m8n8.x4.trans.shared.b16 {%0,%1,%2,%3}, [%4];"
                 : "=r"(a[0]), "=r"(a[1]), "=r"(a[2]), "=r"(a[3]) : "r"(addr));
}
__device__ __forceinline__ void mma16816(float c[4], const uint32_t a[4], const uint32_t b[2]) {
    asm volatile("mma.sync.aligned.m16n8k16.row.col.f32.bf16.bf16.f32 "
                 "{%0,%1,%2,%3}, {%4,%5,%6,%7}, {%8,%9}, {%0,%1,%2,%3};"
                 : "+f"(c[0]), "+f"(c[1]), "+f"(c[2]), "+f"(c[3])
                 : "r"(a[0]), "r"(a[1]), "r"(a[2]), "r"(a[3]), "r"(b[0]), "r"(b[1]));
}
#define CP16(dst, src) \
    asm volatile("cp.async.ca.shared.global [%0], [%1], 16;" :: "r"(dst), "l"(src))
#define CP_COMMIT() asm volatile("cp.async.commit_group;")
#define CP_WAIT(n)  asm volatile("cp.async.wait_group %0;" :: "n"(n))

__global__ __launch_bounds__(256, 2)
void zoe_gemm(float* __restrict__ out) {
    __shared__ __nv_bfloat16 Ah[2][128][APITCH];
    __shared__ __nv_bfloat16 Al[2][128][APITCH];
    __shared__ __nv_bfloat16 Bh[2][16][BPITCH];
    __shared__ __nv_bfloat16 Bl[2][16][BPITCH];

    int tid = threadIdx.x;
    int bm = blockIdx.y * 128;
    int bn = blockIdx.x * 128;

    int ar = tid >> 1;
    int ac = (tid & 1) * 8;
    int br = tid >> 4;
    int bc = (tid & 15) * 8;

    const __nv_bfloat16* pWhi = &g_Whi[(bm + ar) * 256 + ac];
    const __nv_bfloat16* pWlo = &g_Wlo[(bm + ar) * 256 + ac];
    const __nv_bfloat16* pRhi = &g_Rhi[(size_t)br * NP + bn + bc];
    const __nv_bfloat16* pRlo = &g_Rlo[(size_t)br * NP + bn + bc];

    int wid = tid >> 5, lane = tid & 31;
    int wm = (wid >> 2) * 64;
    int wn = (wid & 3) * 32;
    int r8 = lane >> 3, i8 = lane & 7;
    int a_row = wm + (r8 & 1) * 8 + i8;
    int a_col = (r8 >> 1) * 8;
    int b_krow = (r8 & 1) * 8 + i8;
    int b_ncol = wn + (r8 >> 1) * 8;

    float acc[4][4][4];
#pragma unroll
    for (int mt = 0; mt < 4; mt++)
#pragma unroll
        for (int nt = 0; nt < 4; nt++)
#pragma unroll
            for (int e = 0; e < 4; e++) acc[mt][nt][e] = 0.f;

    // prologue: stage 0
    {
        CP16(smaddr(&Ah[0][ar][ac]), pWhi);
        CP16(smaddr(&Al[0][ar][ac]), pWlo);
        CP16(smaddr(&Bh[0][br][bc]), pRhi);
        CP16(smaddr(&Bl[0][br][bc]), pRlo);
        CP_COMMIT();
    }

    const int NSTEP = KPAD / 16;  // 16
    for (int s = 0; s < NSTEP; s++) {
        int buf = s & 1;
        if (s + 1 < NSTEP) {
            int k0 = (s + 1) * 16;
            int nb = buf ^ 1;
            CP16(smaddr(&Ah[nb][ar][ac]), pWhi + k0);
            CP16(smaddr(&Al[nb][ar][ac]), pWlo + k0);
            CP16(smaddr(&Bh[nb][br][bc]), pRhi + (size_t)k0 * NP);
            CP16(smaddr(&Bl[nb][br][bc]), pRlo + (size_t)k0 * NP);
            CP_COMMIT();
            CP_WAIT(1);
        } else {
            CP_WAIT(0);
        }
        __syncthreads();

        uint32_t bhf[4][2], blf[4][2];
#pragma unroll
        for (int pair = 0; pair < 2; pair++) {
            uint32_t t4[4];
            ldsm4t(t4, smaddr(&Bh[buf][b_krow][b_ncol + pair * 16]));
            bhf[pair * 2][0] = t4[0]; bhf[pair * 2][1] = t4[1];
            bhf[pair * 2 + 1][0] = t4[2]; bhf[pair * 2 + 1][1] = t4[3];
            ldsm4t(t4, smaddr(&Bl[buf][b_krow][b_ncol + pair * 16]));
            blf[pair * 2][0] = t4[0]; blf[pair * 2][1] = t4[1];
            blf[pair * 2 + 1][0] = t4[2]; blf[pair * 2 + 1][1] = t4[3];
        }

#pragma unroll
        for (int mt = 0; mt < 4; mt++) {
            uint32_t ahf[4], alf[4];
            ldsm4(ahf, smaddr(&Ah[buf][a_row + mt * 16][a_col]));
            ldsm4(alf, smaddr(&Al[buf][a_row + mt * 16][a_col]));
#pragma unroll
            for (int nt = 0; nt < 4; nt++) {
                mma16816(acc[mt][nt], ahf, bhf[nt]);
                mma16816(acc[mt][nt], ahf, blf[nt]);
                mma16816(acc[mt][nt], alf, bhf[nt]);
            }
        }
        __syncthreads();
    }

    // epilogue
#pragma unroll
    for (int mt = 0; mt < 4; mt++) {
#pragma unroll
        for (int nt = 0; nt < 4; nt++) {
            int l0 = bm + wm + mt * 16 + (lane >> 2);
            int n0 = bn + wn + nt * 8 + (lane & 3) * 2;
#pragma unroll
            for (int e = 0; e < 4; e++) {
                int l = l0 + (e >> 1) * 8;
                int n = n0 + (e & 1);
                if (l < L_LAYERS && n < NCOL) {
                    int t = n / N_THETA;
                    int a = n - t * N_THETA;
                    out[t * (L_LAYERS * N_THETA) + l * N_THETA + a] = acc[mt][nt][e];
                }
            }
        }
    }
}

extern "C" void kernel_launch(void* const* d_in, const int* in_sizes, int n_in,
                              void* d_out, int out_size) {
    const float* vp      = (const float*)d_in[0];
    const float* vs      = (const float*)d_in[1];
    const float* rho     = (const float*)d_in[2];
    const float* theta   = (const float*)d_in[3];
    const float* wavemat = (const float*)d_in[4];
    float* out = (float*)d_out;

    int nblk = (TOTAL + WELEMS + 255) / 256;   // phase1 region + W-split region
    zoe_phase1<<<nblk, 256>>>(vp, vs, rho, theta, wavemat);

    dim3 grid((NCOL + 127) / 128, 2);
    zoe_gemm<<<grid, 256>>>(out);
}

// round 6
// speedup vs baseline: 1.8078x; 1.3269x over previous
#include <cuda_runtime.h>
#include <cuda_fp16.h>
#include <math.h>
#include <stdint.h>

#define L_LAYERS 250
#define N_TRACES 600
#define N_THETA  30
#define NI   249                 // interfaces (ref row 249 is zero -> dropped)
#define NCOL 18000               // N_TRACES * N_THETA
#define NP   18048               // padded R plane pitch (cols)
#define KPAD 256                 // padded K
#define TOTAL (NI * NCOL)
#define WELEMS (256 * 256)

// fp16 planes. __device__ globals are zero-initialized at module load.
// Pad regions (rows >= 249, cols >= 18000) are NEVER written by any kernel,
// so they remain zero across all graph replays.
// R is split (hi + lo, 22 bits combined); W is a single fp16 plane.
__device__ __half g_Rhi[KPAD * NP];
__device__ __half g_Rlo[KPAD * NP];
__device__ __half g_Wh[256 * 256];

__device__ __forceinline__ float sqrt_approx(float x) {
    float r;
    asm("sqrt.approx.f32 %0, %1;" : "=f"(r) : "f"(x));
    return r;
}

// ---------------------------------------------------------------------------
// Phase 1 (fused): exact Zoeppritz Rpp via the Aki & Richards closed form,
// homogeneously rescaled by a1*a2*b1*b2 so the only reciprocal is the final
// divide. Clipping never activates for these input ranges (p*a2 <= 0.836).
// Writes split-fp16 planes r = hi + lo.
// Blocks past the R range convert W fp32 -> fp16 (single plane).
// ---------------------------------------------------------------------------
__global__ void zoe_phase1(const float* __restrict__ vp,
                           const float* __restrict__ vs,
                           const float* __restrict__ rho,
                           const float* __restrict__ theta,
                           const float* __restrict__ W) {
    int gidx = blockIdx.x * 256 + threadIdx.x;

    if (gidx >= TOTAL) {
        int idx = gidx - TOTAL;
        if (idx < WELEMS) {
            int r = idx >> 8, k = idx & 255;
            float v = (r < L_LAYERS && k < L_LAYERS) ? W[r * L_LAYERS + k] : 0.f;
            g_Wh[idx] = __float2half(v);
        }
        return;
    }

    __shared__ float s_sth[N_THETA], s_cth[N_THETA];
    int tid = threadIdx.x;
    if (tid < N_THETA) {
        float sv, cv;
        sincosf(theta[tid], &sv, &cv);
        s_sth[tid] = sv;
        s_cth[tid] = cv;
    }
    __syncthreads();

    int l = gidx / NCOL;
    int n = gidx - l * NCOL;
    int t = n / N_THETA;
    int a = n - t * N_THETA;

    float a1 = vp[l * N_TRACES + t],  a2 = vp[(l + 1) * N_TRACES + t];
    float b1 = vs[l * N_TRACES + t],  b2 = vs[(l + 1) * N_TRACES + t];
    float r1 = rho[l * N_TRACES + t], r2 = rho[(l + 1) * N_TRACES + t];

    float sth = s_sth[a], cth = s_cth[a];
    float p  = __fdividef(sth, a1);
    float p2 = p * p;

    float st2 = p * a2;
    float ct2 = sqrt_approx(fmaxf(1.f - st2 * st2, 0.f));
    float sp1 = p * b1;
    float cp1 = sqrt_approx(fmaxf(1.f - sp1 * sp1, 0.f));
    float sp2 = p * b2;
    float cp2 = sqrt_approx(fmaxf(1.f - sp2 * sp2, 0.f));

    float k1 = 2.f * r1 * (b1 * b1);
    float k2 = 2.f * r2 * (b2 * b2);
    float d  = k2 - k1;
    float dp2 = d * p2;

    float A = (r2 - r1) - dp2;
    float B = r2 - dp2;
    float C = r1 + dp2;

    float X = B * cth * a2;
    float Y = C * ct2 * a1;
    float E = X + Y;
    float F = fmaf(B * cp1, b2, C * cp2 * b1);
    float Z = d * cth * cp2;
    float Aa1b2 = A * a1 * b2;
    float G = Aa1b2 - Z;
    float H = fmaf(-d * ct2, cp1, A * a2 * b1);
    float GHp2 = G * H * p2;
    float D = fmaf(E, F, GHp2);
    float num = fmaf(X - Y, F, -(Aa1b2 + Z) * H * p2);

    float r = __fdividef(num, D);
    __half hi = __float2half(r);
    float lof = r - __half2float(hi);
    g_Rhi[l * NP + n] = hi;
    g_Rlo[l * NP + n] = __float2half(lof);
}

// ---------------------------------------------------------------------------
// Phase 2: out[t, l, a] = sum_k W[l, k] * R[k, n], n = t*30 + a
// fp16 HMMA GEMM, 2-product asymmetric split: acc += Wh*Rh + Wh*Rl.
// M=256, N=18000(pad 18048), K=256. Block 128x128, 8 warps (2x4),
// warp 64x32, m16n8k16. 2-stage cp.async double buffering (proven config).
// ---------------------------------------------------------------------------
#define APITCH 24
#define BPITCH 136

__device__ __forceinline__ uint32_t smaddr(const void* p) {
    return (uint32_t)__cvta_generic_to_shared(p);
}
__device__ __forceinline__ void ldsm4(uint32_t a[4], uint32_t addr) {
    asm volatile("ldmatrix.sync.aligned.m8n8.x4.shared.b16 {%0,%1,%2,%3}, [%4];"
                 : "=r"(a[0]), "=r"(a[1]), "=r"(a[2]), "=r"(a[3]) : "r"(addr));
}
__device__ __forceinline__ void ldsm4t(uint32_t a[4], uint32_t addr) {
    asm volatile("ldmatrix.sync.aligned.m8n8.x4.trans.shared.b16 {%0,%1,%2,%3}, [%4];"
                 : "=r"(a[0]), "=r"(a[1]), "=r"(a[2]), "=r"(a[3]) : "r"(addr));
}
__device__ __forceinline__ void mma16816(float c[4], const uint32_t a[4], const uint32_t b[2]) {
    asm volatile("mma.sync.aligned.m16n8k16.row.col.f32.f16.f16.f32 "
                 "{%0,%1,%2,%3}, {%4,%5,%6,%7}, {%8,%9}, {%0,%1,%2,%3};"
                 : "+f"(c[0]), "+f"(c[1]), "+f"(c[2]), "+f"(c[3])
                 : "r"(a[0]), "r"(a[1]), "r"(a[2]), "r"(a[3]), "r"(b[0]), "r"(b[1]));
}
#define CP16(dst, src) \
    asm volatile("cp.async.ca.shared.global [%0], [%1], 16;" :: "r"(dst), "l"(src))
#define CP_COMMIT() asm volatile("cp.async.commit_group;")
#define CP_WAIT(n)  asm volatile("cp.async.wait_group %0;" :: "n"(n))

__global__ __launch_bounds__(256, 2)
void zoe_gemm(float* __restrict__ out) {
    __shared__ __half Ah[2][128][APITCH];
    __shared__ __half Bh[2][16][BPITCH];
    __shared__ __half Bl[2][16][BPITCH];

    int tid = threadIdx.x;
    int bm = blockIdx.y * 128;
    int bn = blockIdx.x * 128;

    int ar = tid >> 1;
    int ac = (tid & 1) * 8;
    int br = tid >> 4;
    int bc = (tid & 15) * 8;

    const __half* pWh  = &g_Wh[(bm + ar) * 256 + ac];
    const __half* pRhi = &g_Rhi[(size_t)br * NP + bn + bc];
    const __half* pRlo = &g_Rlo[(size_t)br * NP + bn + bc];

    int wid = tid >> 5, lane = tid & 31;
    int wm = (wid >> 2) * 64;
    int wn = (wid & 3) * 32;
    int r8 = lane >> 3, i8 = lane & 7;
    int a_row = wm + (r8 & 1) * 8 + i8;
    int a_col = (r8 >> 1) * 8;
    int b_krow = (r8 & 1) * 8 + i8;
    int b_ncol = wn + (r8 >> 1) * 8;

    float acc[4][4][4];
#pragma unroll
    for (int mt = 0; mt < 4; mt++)
#pragma unroll
        for (int nt = 0; nt < 4; nt++)
#pragma unroll
            for (int e = 0; e < 4; e++) acc[mt][nt][e] = 0.f;

    // prologue: stage 0
    {
        CP16(smaddr(&Ah[0][ar][ac]), pWh);
        CP16(smaddr(&Bh[0][br][bc]), pRhi);
        CP16(smaddr(&Bl[0][br][bc]), pRlo);
        CP_COMMIT();
    }

    const int NSTEP = KPAD / 16;  // 16
    for (int s = 0; s < NSTEP; s++) {
        int buf = s & 1;
        if (s + 1 < NSTEP) {
            int k0 = (s + 1) * 16;
            int nb = buf ^ 1;
            CP16(smaddr(&Ah[nb][ar][ac]), pWh + k0);
            CP16(smaddr(&Bh[nb][br][bc]), pRhi + (size_t)k0 * NP);
            CP16(smaddr(&Bl[nb][br][bc]), pRlo + (size_t)k0 * NP);
            CP_COMMIT();
            CP_WAIT(1);
        } else {
            CP_WAIT(0);
        }
        __syncthreads();

        uint32_t bhf[4][2], blf[4][2];
#pragma unroll
        for (int pair = 0; pair < 2; pair++) {
            uint32_t t4[4];
            ldsm4t(t4, smaddr(&Bh[buf][b_krow][b_ncol + pair * 16]));
            bhf[pair * 2][0] = t4[0]; bhf[pair * 2][1] = t4[1];
            bhf[pair * 2 + 1][0] = t4[2]; bhf[pair * 2 + 1][1] = t4[3];
            ldsm4t(t4, smaddr(&Bl[buf][b_krow][b_ncol + pair * 16]));
            blf[pair * 2][0] = t4[0]; blf[pair * 2][1] = t4[1];
            blf[pair * 2 + 1][0] = t4[2]; blf[pair * 2 + 1][1] = t4[3];
        }

#pragma unroll
        for (int mt = 0; mt < 4; mt++) {
            uint32_t ahf[4];
            ldsm4(ahf, smaddr(&Ah[buf][a_row + mt * 16][a_col]));
#pragma unroll
            for (int nt = 0; nt < 4; nt++) {
                mma16816(acc[mt][nt], ahf, bhf[nt]);
                mma16816(acc[mt][nt], ahf, blf[nt]);
            }
        }
        __syncthreads();
    }

    // epilogue
#pragma unroll
    for (int mt = 0; mt < 4; mt++) {
#pragma unroll
        for (int nt = 0; nt < 4; nt++) {
            int l0 = bm + wm + mt * 16 + (lane >> 2);
            int n0 = bn + wn + nt * 8 + (lane & 3) * 2;
#pragma unroll
            for (int e = 0; e < 4; e++) {
                int l = l0 + (e >> 1) * 8;
                int n = n0 + (e & 1);
                if (l < L_LAYERS && n < NCOL) {
                    int t = n / N_THETA;
                    int a = n - t * N_THETA;
                    out[t * (L_LAYERS * N_THETA) + l * N_THETA + a] = acc[mt][nt][e];
                }
            }
        }
    }
}

extern "C" void kernel_launch(void* const* d_in, const int* in_sizes, int n_in,
                              void* d_out, int out_size) {
    const float* vp      = (const float*)d_in[0];
    const float* vs      = (const float*)d_in[1];
    const float* rho     = (const float*)d_in[2];
    const float* theta   = (const float*)d_in[3];
    const float* wavemat = (const float*)d_in[4];
    float* out = (float*)d_out;

    int nblk = (TOTAL + WELEMS + 255) / 256;
    zoe_phase1<<<nblk, 256>>>(vp, vs, rho, theta, wavemat);

    dim3 grid((NCOL + 127) / 128, 2);
    zoe_gemm<<<grid, 256>>>(out);
}

// round 7
// speedup vs baseline: 2.1498x; 1.1892x over previous
#include <cuda_runtime.h>
#include <cuda_fp16.h>
#include <math.h>
#include <stdint.h>

#define L_LAYERS 250
#define N_TRACES 600
#define N_THETA  30
#define NI   249                 // interfaces (ref row 249 is zero -> dropped)
#define NCOL 18000               // N_TRACES * N_THETA
#define NP   18048               // padded R plane pitch (cols)
#define KPAD 256                 // padded K
#define TOTAL (NI * NCOL)
#define HTOTAL (TOTAL / 2)       // angle-pair count
#define WELEMS (256 * 256)

// fp16 planes. __device__ globals are zero-initialized at module load.
// Pad regions (rows >= 249, cols >= 18000) are NEVER written by any kernel,
// so they remain zero across all graph replays.
__device__ __half g_Rhi[KPAD * NP];
__device__ __half g_Rlo[KPAD * NP];
__device__ __half g_Wh[256 * 256];

__device__ __forceinline__ float sqrt_approx(float x) {
    float r;
    asm("sqrt.approx.f32 %0, %1;" : "=f"(r) : "f"(x));
    return r;
}

// ---------------------------------------------------------------------------
// Phase 1 (fused): exact Zoeppritz Rpp via the Aki & Richards closed form,
// rescaled by a1*a2*b1*b2 (single reciprocal: 1/a1; single final divide per
// angle). One thread computes TWO adjacent angles -> __half2 stores.
// Clipping never activates for these input ranges (p*a2 <= 0.836).
// Blocks past the pair range convert W fp32 -> fp16.
// ---------------------------------------------------------------------------
__global__ void zoe_phase1(const float* __restrict__ vp,
                           const float* __restrict__ vs,
                           const float* __restrict__ rho,
                           const float* __restrict__ theta,
                           const float* __restrict__ W) {
    int gidx = blockIdx.x * 256 + threadIdx.x;

    if (gidx >= HTOTAL) {
        int idx = gidx - HTOTAL;
        if (idx < WELEMS) {
            int r = idx >> 8, k = idx & 255;
            float v = (r < L_LAYERS && k < L_LAYERS) ? W[r * L_LAYERS + k] : 0.f;
            g_Wh[idx] = __float2half(v);
        }
        return;
    }

    __shared__ float s_sth[N_THETA], s_cth[N_THETA];
    int tid = threadIdx.x;
    if (tid < N_THETA) {
        float sv, cv;
        sincosf(theta[tid], &sv, &cv);
        s_sth[tid] = sv;
        s_cth[tid] = cv;
    }
    __syncthreads();

    int l   = gidx / (NCOL / 2);
    int rem = gidx - l * (NCOL / 2);
    int t   = rem / (N_THETA / 2);
    int ap  = rem - t * (N_THETA / 2);
    int a0  = ap * 2;
    int n   = t * N_THETA + a0;

    float a1 = vp[l * N_TRACES + t],  a2 = vp[(l + 1) * N_TRACES + t];
    float b1 = vs[l * N_TRACES + t],  b2 = vs[(l + 1) * N_TRACES + t];
    float r1 = rho[l * N_TRACES + t], r2 = rho[(l + 1) * N_TRACES + t];

    float inva1 = __fdividef(1.f, a1);
    float k1 = 2.f * r1 * (b1 * b1);
    float k2 = 2.f * r2 * (b2 * b2);
    float d  = k2 - k1;
    float drho = r2 - r1;
    float a1b2 = a1 * b2;
    float a2b1 = a2 * b1;

    float rhv[2], rlv[2];
#pragma unroll
    for (int j = 0; j < 2; j++) {
        float sth = s_sth[a0 + j], cth = s_cth[a0 + j];
        float p  = sth * inva1;
        float p2 = p * p;

        float st2 = p * a2;
        float ct2 = sqrt_approx(fmaxf(1.f - st2 * st2, 0.f));
        float sp1 = p * b1;
        float cp1 = sqrt_approx(fmaxf(1.f - sp1 * sp1, 0.f));
        float sp2 = p * b2;
        float cp2 = sqrt_approx(fmaxf(1.f - sp2 * sp2, 0.f));

        float dp2 = d * p2;
        float A = drho - dp2;
        float B = r2 - dp2;
        float C = r1 + dp2;

        float X = B * cth * a2;
        float Y = C * ct2 * a1;
        float E = X + Y;
        float F = fmaf(B * cp1, b2, C * cp2 * b1);
        float Z = d * cth * cp2;
        float Aa1b2 = A * a1b2;
        float G = Aa1b2 - Z;
        float H = fmaf(-d * ct2, cp1, A * a2b1);
        float D = fmaf(E, F, G * H * p2);
        float num = fmaf(X - Y, F, -(Aa1b2 + Z) * H * p2);

        float r = __fdividef(num, D);
        __half hi = __float2half(r);
        rhv[j] = __half2float(hi);
        rlv[j] = r - rhv[j];
    }

    size_t o = ((size_t)l * NP + n) >> 1;
    reinterpret_cast<__half2*>(g_Rhi)[o] =
        __halves2half2(__float2half(rhv[0]), __float2half(rhv[1]));
    reinterpret_cast<__half2*>(g_Rlo)[o] =
        __halves2half2(__float2half(rlv[0]), __float2half(rlv[1]));
}

// ---------------------------------------------------------------------------
// Phase 2: out[t, l, a] = sum_k W[l, k] * R[k, n], n = t*30 + a
// fp16 HMMA GEMM, 2-product asymmetric split: acc += Wh*Rh + Wh*Rl.
// M=256, N=18000(pad 18048), K=256. Block 128x128, 8 warps (2x4),
// warp 64x32, m16n8k16. 4-stage cp.async pipeline, FULLY UNROLLED so all
// stage indices (s & 3) and smem offsets are compile-time constants.
// One __syncthreads per k-step; prefetch distance 3 steps.
// ---------------------------------------------------------------------------
#define APITCH 24
#define BPITCH 136
#define ASTG (128 * APITCH)          // halves per A stage: 3072
#define BSTG (16 * BPITCH)           // halves per B stage: 2176
#define SMEM_BYTES ((4 * ASTG + 8 * BSTG) * 2)   // 59392

__device__ __forceinline__ uint32_t smaddr(const void* p) {
    return (uint32_t)__cvta_generic_to_shared(p);
}
__device__ __forceinline__ void ldsm4(uint32_t a[4], uint32_t addr) {
    asm volatile("ldmatrix.sync.aligned.m8n8.x4.shared.b16 {%0,%1,%2,%3}, [%4];"
                 : "=r"(a[0]), "=r"(a[1]), "=r"(a[2]), "=r"(a[3]) : "r"(addr));
}
__device__ __forceinline__ void ldsm4t(uint32_t a[4], uint32_t addr) {
    asm volatile("ldmatrix.sync.aligned.m8n8.x4.trans.shared.b16 {%0,%1,%2,%3}, [%4];"
                 : "=r"(a[0]), "=r"(a[1]), "=r"(a[2]), "=r"(a[3]) : "r"(addr));
}
__device__ __forceinline__ void mma16816(float c[4], const uint32_t a[4], const uint32_t b[2]) {
    asm volatile("mma.sync.aligned.m16n8k16.row.col.f32.f16.f16.f32 "
                 "{%0,%1,%2,%3}, {%4,%5,%6,%7}, {%8,%9}, {%0,%1,%2,%3};"
                 : "+f"(c[0]), "+f"(c[1]), "+f"(c[2]), "+f"(c[3])
                 : "r"(a[0]), "r"(a[1]), "r"(a[2]), "r"(a[3]), "r"(b[0]), "r"(b[1]));
}
#define CP16(dst, src) \
    asm volatile("cp.async.ca.shared.global [%0], [%1], 16;" :: "r"(dst), "l"(src))
#define CP_COMMIT() asm volatile("cp.async.commit_group;")
#define CP_WAIT(n)  asm volatile("cp.async.wait_group %0;" :: "n"(n))

__global__ __launch_bounds__(256, 2)
void zoe_gemm(float* __restrict__ out) {
    extern __shared__ __half sm[];
    __half* Ah = sm;                      // 4 * ASTG halves
    __half* Bh = sm + 4 * ASTG;           // 4 * BSTG halves
    __half* Bl = Bh + 4 * BSTG;           // 4 * BSTG halves

    int tid = threadIdx.x;
    int bm = blockIdx.y * 128;
    int bn = blockIdx.x * 128;

    int ar = tid >> 1;
    int ac = (tid & 1) * 8;
    int br = tid >> 4;
    int bc = (tid & 15) * 8;

    const __half* pWh  = &g_Wh[(bm + ar) * 256 + ac];
    const __half* pRhi = &g_Rhi[(size_t)br * NP + bn + bc];
    const __half* pRlo = &g_Rlo[(size_t)br * NP + bn + bc];

    uint32_t sA  = smaddr(&Ah[ar * APITCH + ac]);
    uint32_t sB  = smaddr(&Bh[br * BPITCH + bc]);
    uint32_t sBl = smaddr(&Bl[br * BPITCH + bc]);

    int wid = tid >> 5, lane = tid & 31;
    int wm = (wid >> 2) * 64;
    int wn = (wid & 3) * 32;
    int r8 = lane >> 3, i8 = lane & 7;
    int a_row = wm + (r8 & 1) * 8 + i8;
    int a_col = (r8 >> 1) * 8;
    int b_krow = (r8 & 1) * 8 + i8;
    int b_ncol = wn + (r8 >> 1) * 8;

    uint32_t sAf = smaddr(&Ah[a_row * APITCH + a_col]);
    uint32_t sBf = smaddr(&Bh[b_krow * BPITCH + b_ncol]);
    uint32_t sBlf = smaddr(&Bl[b_krow * BPITCH + b_ncol]);

    float acc[4][4][4];
#pragma unroll
    for (int mt = 0; mt < 4; mt++)
#pragma unroll
        for (int nt = 0; nt < 4; nt++)
#pragma unroll
            for (int e = 0; e < 4; e++) acc[mt][nt][e] = 0.f;

    const int NSTEP = KPAD / 16;  // 16

    // prologue: stages 0..2
#pragma unroll
    for (int s = 0; s < 3; s++) {
        int k0 = s * 16;
        CP16(sA  + s * (ASTG * 2), pWh + k0);
        CP16(sB  + s * (BSTG * 2), pRhi + (size_t)k0 * NP);
        CP16(sBl + s * (BSTG * 2), pRlo + (size_t)k0 * NP);
        CP_COMMIT();
    }

#pragma unroll
    for (int s = 0; s < NSTEP; s++) {
        // wait until stage s has landed
        if (s <= NSTEP - 3) { CP_WAIT(2); }
        else if (s == NSTEP - 2) { CP_WAIT(1); }
        else { CP_WAIT(0); }
        __syncthreads();   // also proves step s-1 readers of buffer (s+3)&3 done

        // refill: stage s+3 into buffer (s+3)&3
        if (s + 3 < NSTEP) {
            int k0 = (s + 3) * 16;
            int nb = (s + 3) & 3;
            CP16(sA  + nb * (ASTG * 2), pWh + k0);
            CP16(sB  + nb * (BSTG * 2), pRhi + (size_t)k0 * NP);
            CP16(sBl + nb * (BSTG * 2), pRlo + (size_t)k0 * NP);
            CP_COMMIT();
        }

        int buf = s & 3;
        uint32_t aBase  = sAf  + buf * (ASTG * 2);
        uint32_t bBase  = sBf  + buf * (BSTG * 2);
        uint32_t blBase = sBlf + buf * (BSTG * 2);

        uint32_t bhf[4][2], blf[4][2];
#pragma unroll
        for (int pair = 0; pair < 2; pair++) {
            uint32_t t4[4];
            ldsm4t(t4, bBase + pair * 32);
            bhf[pair * 2][0] = t4[0]; bhf[pair * 2][1] = t4[1];
            bhf[pair * 2 + 1][0] = t4[2]; bhf[pair * 2 + 1][1] = t4[3];
            ldsm4t(t4, blBase + pair * 32);
            blf[pair * 2][0] = t4[0]; blf[pair * 2][1] = t4[1];
            blf[pair * 2 + 1][0] = t4[2]; blf[pair * 2 + 1][1] = t4[3];
        }

#pragma unroll
        for (int mt = 0; mt < 4; mt++) {
            uint32_t ahf[4];
            ldsm4(ahf, aBase + mt * 16 * (APITCH * 2));
#pragma unroll
            for (int nt = 0; nt < 4; nt++) {
                mma16816(acc[mt][nt], ahf, bhf[nt]);
                mma16816(acc[mt][nt], ahf, blf[nt]);
            }
        }
    }

    // epilogue
#pragma unroll
    for (int mt = 0; mt < 4; mt++) {
#pragma unroll
        for (int nt = 0; nt < 4; nt++) {
            int l0 = bm + wm + mt * 16 + (lane >> 2);
            int n0 = bn + wn + nt * 8 + (lane & 3) * 2;
#pragma unroll
            for (int e = 0; e < 4; e++) {
                int l = l0 + (e >> 1) * 8;
                int n = n0 + (e & 1);
                if (l < L_LAYERS && n < NCOL) {
                    int t = n / N_THETA;
                    int a = n - t * N_THETA;
                    out[t * (L_LAYERS * N_THETA) + l * N_THETA + a] = acc[mt][nt][e];
                }
            }
        }
    }
}

extern "C" void kernel_launch(void* const* d_in, const int* in_sizes, int n_in,
                              void* d_out, int out_size) {
    const float* vp      = (const float*)d_in[0];
    const float* vs      = (const float*)d_in[1];
    const float* rho     = (const float*)d_in[2];
    const float* theta   = (const float*)d_in[3];
    const float* wavemat = (const float*)d_in[4];
    float* out = (float*)d_out;

    // idempotent, called every launch (no static guards allowed)
    cudaFuncSetAttribute(zoe_gemm, cudaFuncAttributeMaxDynamicSharedMemorySize,
                         SMEM_BYTES);

    int nblk = (HTOTAL + WELEMS + 255) / 256;
    zoe_phase1<<<nblk, 256>>>(vp, vs, rho, theta, wavemat);

    dim3 grid((NCOL + 127) / 128, 2);
    zoe_gemm<<<grid, 256, SMEM_BYTES>>>(out);
}

// round 8
// speedup vs baseline: 2.2261x; 1.0355x over previous
#include <cuda_runtime.h>
#include <cuda_fp16.h>
#include <math.h>
#include <stdint.h>

#define L_LAYERS 250
#define N_TRACES 600
#define N_THETA  30
#define NI   249                 // interfaces (ref row 249 is zero -> dropped)
#define NCOL 18000               // N_TRACES * N_THETA
#define NP   18048               // padded R plane pitch (cols)
#define KPAD 256                 // padded K
#define TOTAL (NI * NCOL)
#define HTOTAL (TOTAL / 2)       // angle-pair count
#define WELEMS (256 * 256)

// fp16 planes. __device__ globals are zero-initialized at module load.
// Pad regions (rows >= 249, cols >= 18000) are NEVER written by any kernel,
// so they remain zero across all graph replays.
__device__ __half g_Rh[KPAD * NP];
__device__ __half g_Wh[256 * 256];

__device__ __forceinline__ float sqrt_approx(float x) {
    float r;
    asm("sqrt.approx.f32 %0, %1;" : "=f"(r) : "f"(x));
    return r;
}

// ---------------------------------------------------------------------------
// Phase 1 (fused): exact Zoeppritz Rpp via the Aki & Richards closed form,
// rescaled by a1*a2*b1*b2 (one rcp + one final divide per angle). One thread
// computes TWO adjacent angles -> __half2 store. Clipping never activates for
// these input ranges (p*a2 <= 0.836).
// Blocks past the pair range convert W fp32 -> fp16.
// ---------------------------------------------------------------------------
__global__ void zoe_phase1(const float* __restrict__ vp,
                           const float* __restrict__ vs,
                           const float* __restrict__ rho,
                           const float* __restrict__ theta,
                           const float* __restrict__ W) {
    int gidx = blockIdx.x * 256 + threadIdx.x;

    if (gidx >= HTOTAL) {
        int idx = gidx - HTOTAL;
        if (idx < WELEMS) {
            int r = idx >> 8, k = idx & 255;
            float v = (r < L_LAYERS && k < L_LAYERS) ? W[r * L_LAYERS + k] : 0.f;
            g_Wh[idx] = __float2half(v);
        }
        return;
    }

    __shared__ float s_sth[N_THETA], s_cth[N_THETA];
    int tid = threadIdx.x;
    if (tid < N_THETA) {
        float sv, cv;
        sincosf(theta[tid], &sv, &cv);
        s_sth[tid] = sv;
        s_cth[tid] = cv;
    }
    __syncthreads();

    int l   = gidx / (NCOL / 2);
    int rem = gidx - l * (NCOL / 2);
    int t   = rem / (N_THETA / 2);
    int ap  = rem - t * (N_THETA / 2);
    int a0  = ap * 2;
    int n   = t * N_THETA + a0;

    float a1 = vp[l * N_TRACES + t],  a2 = vp[(l + 1) * N_TRACES + t];
    float b1 = vs[l * N_TRACES + t],  b2 = vs[(l + 1) * N_TRACES + t];
    float r1 = rho[l * N_TRACES + t], r2 = rho[(l + 1) * N_TRACES + t];

    float inva1 = __fdividef(1.f, a1);
    float k1 = 2.f * r1 * (b1 * b1);
    float k2 = 2.f * r2 * (b2 * b2);
    float d  = k2 - k1;
    float drho = r2 - r1;
    float a1b2 = a1 * b2;
    float a2b1 = a2 * b1;

    float rv[2];
#pragma unroll
    for (int j = 0; j < 2; j++) {
        float sth = s_sth[a0 + j], cth = s_cth[a0 + j];
        float p  = sth * inva1;
        float p2 = p * p;

        float st2 = p * a2;
        float ct2 = sqrt_approx(fmaxf(1.f - st2 * st2, 0.f));
        float sp1 = p * b1;
        float cp1 = sqrt_approx(fmaxf(1.f - sp1 * sp1, 0.f));
        float sp2 = p * b2;
        float cp2 = sqrt_approx(fmaxf(1.f - sp2 * sp2, 0.f));

        float dp2 = d * p2;
        float A = drho - dp2;
        float B = r2 - dp2;
        float C = r1 + dp2;

        float X = B * cth * a2;
        float Y = C * ct2 * a1;
        float E = X + Y;
        float F = fmaf(B * cp1, b2, C * cp2 * b1);
        float Z = d * cth * cp2;
        float Aa1b2 = A * a1b2;
        float G = Aa1b2 - Z;
        float H = fmaf(-d * ct2, cp1, A * a2b1);
        float D = fmaf(E, F, G * H * p2);
        float num = fmaf(X - Y, F, -(Aa1b2 + Z) * H * p2);

        rv[j] = __fdividef(num, D);
    }

    size_t o = ((size_t)l * NP + n) >> 1;
    reinterpret_cast<__half2*>(g_Rh)[o] =
        __halves2half2(__float2half(rv[0]), __float2half(rv[1]));
}

// ---------------------------------------------------------------------------
// Phase 2: out[t, l, a] = sum_k W[l, k] * R[k, n], n = t*30 + a
// Pure-fp16 HMMA GEMM: acc += Wh*Rh (fp32 accumulate).
// M=256, N=18000(pad 18048), K=256. Block 128x128, 8 warps (2x4),
// warp 64x32, m16n8k16. 4-stage cp.async pipeline, fully unrolled,
// one __syncthreads per k-step, prefetch distance 3.
// ---------------------------------------------------------------------------
#define APITCH 24
#define BPITCH 136
#define ASTG (128 * APITCH)          // halves per A stage: 3072
#define BSTG (16 * BPITCH)           // halves per B stage: 2176
#define SMEM_BYTES ((4 * ASTG + 4 * BSTG) * 2)   // 41984

__device__ __forceinline__ uint32_t smaddr(const void* p) {
    return (uint32_t)__cvta_generic_to_shared(p);
}
__device__ __forceinline__ void ldsm4(uint32_t a[4], uint32_t addr) {
    asm volatile("ldmatrix.sync.aligned.m8n8.x4.shared.b16 {%0,%1,%2,%3}, [%4];"
                 : "=r"(a[0]), "=r"(a[1]), "=r"(a[2]), "=r"(a[3]) : "r"(addr));
}
__device__ __forceinline__ void ldsm4t(uint32_t a[4], uint32_t addr) {
    asm volatile("ldmatrix.sync.aligned.m8n8.x4.trans.shared.b16 {%0,%1,%2,%3}, [%4];"
                 : "=r"(a[0]), "=r"(a[1]), "=r"(a[2]), "=r"(a[3]) : "r"(addr));
}
__device__ __forceinline__ void mma16816(float c[4], const uint32_t a[4], const uint32_t b[2]) {
    asm volatile("mma.sync.aligned.m16n8k16.row.col.f32.f16.f16.f32 "
                 "{%0,%1,%2,%3}, {%4,%5,%6,%7}, {%8,%9}, {%0,%1,%2,%3};"
                 : "+f"(c[0]), "+f"(c[1]), "+f"(c[2]), "+f"(c[3])
                 : "r"(a[0]), "r"(a[1]), "r"(a[2]), "r"(a[3]), "r"(b[0]), "r"(b[1]));
}
#define CP16(dst, src) \
    asm volatile("cp.async.ca.shared.global [%0], [%1], 16;" :: "r"(dst), "l"(src))
#define CP_COMMIT() asm volatile("cp.async.commit_group;")
#define CP_WAIT(n)  asm volatile("cp.async.wait_group %0;" :: "n"(n))

__global__ __launch_bounds__(256, 2)
void zoe_gemm(float* __restrict__ out) {
    extern __shared__ __half sm[];
    __half* Ah = sm;                      // 4 * ASTG halves
    __half* Bh = sm + 4 * ASTG;           // 4 * BSTG halves

    int tid = threadIdx.x;
    int bm = blockIdx.y * 128;
    int bn = blockIdx.x * 128;

    int ar = tid >> 1;
    int ac = (tid & 1) * 8;
    int br = tid >> 4;
    int bc = (tid & 15) * 8;

    const __half* pWh = &g_Wh[(bm + ar) * 256 + ac];
    const __half* pRh = &g_Rh[(size_t)br * NP + bn + bc];

    uint32_t sA = smaddr(&Ah[ar * APITCH + ac]);
    uint32_t sB = smaddr(&Bh[br * BPITCH + bc]);

    int wid = tid >> 5, lane = tid & 31;
    int wm = (wid >> 2) * 64;
    int wn = (wid & 3) * 32;
    int r8 = lane >> 3, i8 = lane & 7;
    int a_row = wm + (r8 & 1) * 8 + i8;
    int a_col = (r8 >> 1) * 8;
    int b_krow = (r8 & 1) * 8 + i8;
    int b_ncol = wn + (r8 >> 1) * 8;

    uint32_t sAf = smaddr(&Ah[a_row * APITCH + a_col]);
    uint32_t sBf = smaddr(&Bh[b_krow * BPITCH + b_ncol]);

    float acc[4][4][4];
#pragma unroll
    for (int mt = 0; mt < 4; mt++)
#pragma unroll
        for (int nt = 0; nt < 4; nt++)
#pragma unroll
            for (int e = 0; e < 4; e++) acc[mt][nt][e] = 0.f;

    const int NSTEP = KPAD / 16;  // 16

    // prologue: stages 0..2
#pragma unroll
    for (int s = 0; s < 3; s++) {
        int k0 = s * 16;
        CP16(sA + s * (ASTG * 2), pWh + k0);
        CP16(sB + s * (BSTG * 2), pRh + (size_t)k0 * NP);
        CP_COMMIT();
    }

#pragma unroll
    for (int s = 0; s < NSTEP; s++) {
        if (s <= NSTEP - 3) { CP_WAIT(2); }
        else if (s == NSTEP - 2) { CP_WAIT(1); }
        else { CP_WAIT(0); }
        __syncthreads();   // also proves step s-1 readers of buffer (s+3)&3 done

        if (s + 3 < NSTEP) {
            int k0 = (s + 3) * 16;
            int nb = (s + 3) & 3;
            CP16(sA + nb * (ASTG * 2), pWh + k0);
            CP16(sB + nb * (BSTG * 2), pRh + (size_t)k0 * NP);
            CP_COMMIT();
        }

        int buf = s & 3;
        uint32_t aBase = sAf + buf * (ASTG * 2);
        uint32_t bBase = sBf + buf * (BSTG * 2);

        uint32_t bhf[4][2];
#pragma unroll
        for (int pair = 0; pair < 2; pair++) {
            uint32_t t4[4];
            ldsm4t(t4, bBase + pair * 32);
            bhf[pair * 2][0] = t4[0]; bhf[pair * 2][1] = t4[1];
            bhf[pair * 2 + 1][0] = t4[2]; bhf[pair * 2 + 1][1] = t4[3];
        }

#pragma unroll
        for (int mt = 0; mt < 4; mt++) {
            uint32_t ahf[4];
            ldsm4(ahf, aBase + mt * 16 * (APITCH * 2));
#pragma unroll
            for (int nt = 0; nt < 4; nt++) {
                mma16816(acc[mt][nt], ahf, bhf[nt]);
            }
        }
    }

    // epilogue
#pragma unroll
    for (int mt = 0; mt < 4; mt++) {
#pragma unroll
        for (int nt = 0; nt < 4; nt++) {
            int l0 = bm + wm + mt * 16 + (lane >> 2);
            int n0 = bn + wn + nt * 8 + (lane & 3) * 2;
#pragma unroll
            for (int e = 0; e < 4; e++) {
                int l = l0 + (e >> 1) * 8;
                int n = n0 + (e & 1);
                if (l < L_LAYERS && n < NCOL) {
                    int t = n / N_THETA;
                    int a = n - t * N_THETA;
                    out[t * (L_LAYERS * N_THETA) + l * N_THETA + a] = acc[mt][nt][e];
                }
            }
        }
    }
}

extern "C" void kernel_launch(void* const* d_in, const int* in_sizes, int n_in,
                              void* d_out, int out_size) {
    const float* vp      = (const float*)d_in[0];
    const float* vs      = (const float*)d_in[1];
    const float* rho     = (const float*)d_in[2];
    const float* theta   = (const float*)d_in[3];
    const float* wavemat = (const float*)d_in[4];
    float* out = (float*)d_out;

    cudaFuncSetAttribute(zoe_gemm, cudaFuncAttributeMaxDynamicSharedMemorySize,
                         SMEM_BYTES);

    int nblk = (HTOTAL + WELEMS + 255) / 256;
    zoe_phase1<<<nblk, 256>>>(vp, vs, rho, theta, wavemat);

    dim3 grid((NCOL + 127) / 128, 2);
    zoe_gemm<<<grid, 256, SMEM_BYTES>>>(out);
}

// round 9
// speedup vs baseline: 2.2601x; 1.0153x over previous
#include <cuda_runtime.h>
#include <cuda_fp16.h>
#include <math.h>
#include <stdint.h>

#define L_LAYERS 250
#define N_TRACES 600
#define N_THETA  30
#define NI   249                 // interfaces (ref row 249 is zero -> dropped)
#define NCOL 18000               // N_TRACES * N_THETA
#define NP   18048               // padded R plane pitch (cols)
#define KPAD 256                 // padded K
#define TOTAL (NI * NCOL)
#define HTOTAL (TOTAL / 2)       // angle-pair count
#define WELEMS (256 * 256)

// fp16 planes. __device__ globals are zero-initialized at module load.
// Pad regions (rows >= 249, cols >= 18000) are NEVER written by any kernel,
// so they remain zero across all graph replays.
__device__ __half g_Rh[KPAD * NP];
__device__ __half g_Wh[256 * 256];

__device__ __forceinline__ float sqrt_approx(float x) {
    float r;
    asm("sqrt.approx.f32 %0, %1;" : "=f"(r) : "f"(x));
    return r;
}

// ---------------------------------------------------------------------------
// Phase 1 (fused): exact Zoeppritz Rpp via the Aki & Richards closed form,
// rescaled by a1*a2*b1*b2 (one rcp + one final divide per angle). One thread
// computes TWO adjacent angles -> __half2 store. Clipping never activates for
// these input ranges (p*a2 <= 0.836).
// Blocks past the pair range convert W fp32 -> fp16.
// ---------------------------------------------------------------------------
__global__ void zoe_phase1(const float* __restrict__ vp,
                           const float* __restrict__ vs,
                           const float* __restrict__ rho,
                           const float* __restrict__ theta,
                           const float* __restrict__ W) {
    int gidx = blockIdx.x * 256 + threadIdx.x;

    if (gidx >= HTOTAL) {
        int idx = gidx - HTOTAL;
        if (idx < WELEMS) {
            int r = idx >> 8, k = idx & 255;
            float v = (r < L_LAYERS && k < L_LAYERS) ? W[r * L_LAYERS + k] : 0.f;
            g_Wh[idx] = __float2half(v);
        }
        return;
    }

    __shared__ float s_sth[N_THETA], s_cth[N_THETA];
    int tid = threadIdx.x;
    if (tid < N_THETA) {
        float sv, cv;
        sincosf(theta[tid], &sv, &cv);
        s_sth[tid] = sv;
        s_cth[tid] = cv;
    }
    __syncthreads();

    int l   = gidx / (NCOL / 2);
    int rem = gidx - l * (NCOL / 2);
    int t   = rem / (N_THETA / 2);
    int ap  = rem - t * (N_THETA / 2);
    int a0  = ap * 2;
    int n   = t * N_THETA + a0;

    float a1 = vp[l * N_TRACES + t],  a2 = vp[(l + 1) * N_TRACES + t];
    float b1 = vs[l * N_TRACES + t],  b2 = vs[(l + 1) * N_TRACES + t];
    float r1 = rho[l * N_TRACES + t], r2 = rho[(l + 1) * N_TRACES + t];

    float inva1 = __fdividef(1.f, a1);
    float k1 = 2.f * r1 * (b1 * b1);
    float k2 = 2.f * r2 * (b2 * b2);
    float d  = k2 - k1;
    float drho = r2 - r1;
    float a1b2 = a1 * b2;
    float a2b1 = a2 * b1;

    float rv[2];
#pragma unroll
    for (int j = 0; j < 2; j++) {
        float sth = s_sth[a0 + j], cth = s_cth[a0 + j];
        float p  = sth * inva1;
        float p2 = p * p;

        float st2 = p * a2;
        float ct2 = sqrt_approx(fmaxf(1.f - st2 * st2, 0.f));
        float sp1 = p * b1;
        float cp1 = sqrt_approx(fmaxf(1.f - sp1 * sp1, 0.f));
        float sp2 = p * b2;
        float cp2 = sqrt_approx(fmaxf(1.f - sp2 * sp2, 0.f));

        float dp2 = d * p2;
        float A = drho - dp2;
        float B = r2 - dp2;
        float C = r1 + dp2;

        float X = B * cth * a2;
        float Y = C * ct2 * a1;
        float E = X + Y;
        float F = fmaf(B * cp1, b2, C * cp2 * b1);
        float Z = d * cth * cp2;
        float Aa1b2 = A * a1b2;
        float G = Aa1b2 - Z;
        float H = fmaf(-d * ct2, cp1, A * a2b1);
        float D = fmaf(E, F, G * H * p2);
        float num = fmaf(X - Y, F, -(Aa1b2 + Z) * H * p2);

        rv[j] = __fdividef(num, D);
    }

    size_t o = ((size_t)l * NP + n) >> 1;
    reinterpret_cast<__half2*>(g_Rh)[o] =
        __halves2half2(__float2half(rv[0]), __float2half(rv[1]));
}

// ---------------------------------------------------------------------------
// Phase 2: out[t, l, a] = sum_k W[l, k] * R[k, n], n = t*30 + a
// Pure-fp16 HMMA GEMM: acc += Wh*Rh (fp32 accumulate).
// M=256, N=18000(pad 18048), K=256.
// Block 64x128, 128 threads (4 warps 2x2), warp tile 32x64, BK=32 per stage,
// 8 k-steps, 4-stage cp.async pipeline fully unrolled, 1 syncthreads/step.
// Grid 141x4 = 564 blocks -> 4 independent blocks/SM (latency overlap).
// ---------------------------------------------------------------------------
#define BM 64
#define BN 128
#define BK 32
#define APITCH 40                    // 32 + 8 pad halves -> 80B rows
#define BPITCH 136                   // 128 + 8 pad halves -> 272B rows
#define ASTG (BM * APITCH)           // 2560 halves per A stage
#define BSTG (BK * BPITCH)           // 4352 halves per B stage
#define SMEM_BYTES ((4 * ASTG + 4 * BSTG) * 2)   // 55296

__device__ __forceinline__ uint32_t smaddr(const void* p) {
    return (uint32_t)__cvta_generic_to_shared(p);
}
__device__ __forceinline__ void ldsm4(uint32_t a[4], uint32_t addr) {
    asm volatile("ldmatrix.sync.aligned.m8n8.x4.shared.b16 {%0,%1,%2,%3}, [%4];"
                 : "=r"(a[0]), "=r"(a[1]), "=r"(a[2]), "=r"(a[3]) : "r"(addr));
}
__device__ __forceinline__ void ldsm4t(uint32_t a[4], uint32_t addr) {
    asm volatile("ldmatrix.sync.aligned.m8n8.x4.trans.shared.b16 {%0,%1,%2,%3}, [%4];"
                 : "=r"(a[0]), "=r"(a[1]), "=r"(a[2]), "=r"(a[3]) : "r"(addr));
}
__device__ __forceinline__ void mma16816(float c[4], const uint32_t a[4], const uint32_t b[2]) {
    asm volatile("mma.sync.aligned.m16n8k16.row.col.f32.f16.f16.f32 "
                 "{%0,%1,%2,%3}, {%4,%5,%6,%7}, {%8,%9}, {%0,%1,%2,%3};"
                 : "+f"(c[0]), "+f"(c[1]), "+f"(c[2]), "+f"(c[3])
                 : "r"(a[0]), "r"(a[1]), "r"(a[2]), "r"(a[3]), "r"(b[0]), "r"(b[1]));
}
#define CP16(dst, src) \
    asm volatile("cp.async.ca.shared.global [%0], [%1], 16;" :: "r"(dst), "l"(src))
#define CP_COMMIT() asm volatile("cp.async.commit_group;")
#define CP_WAIT(n)  asm volatile("cp.async.wait_group %0;" :: "n"(n))

__global__ __launch_bounds__(128, 4)
void zoe_gemm(float* __restrict__ out) {
    extern __shared__ __half sm[];
    __half* Ah = sm;                      // 4 * ASTG halves
    __half* Bh = sm + 4 * ASTG;           // 4 * BSTG halves

    int tid = threadIdx.x;
    int bm = blockIdx.y * BM;
    int bn = blockIdx.x * BN;

    // ---- fill mappings (128 threads) ----
    // A stage: 64 rows x 32 k = 256 CP16 -> 2 per thread (rows r, r+32)
    int a_row0 = tid >> 2;            // 0..31
    int a_chk  = (tid & 3) * 8;       // k offset 0,8,16,24
    // B stage: 32 k-rows x 128 n = 512 CP16 -> 4 per thread
    // e = tid + i*128: krow = e>>4 (0..31), nchunk = (e&15)*8
    const __half* pWh = &g_Wh[(bm + a_row0) * 256 + a_chk];
    const __half* pRh = &g_Rh[0] + bn;

    uint32_t sA = smaddr(&Ah[a_row0 * APITCH + a_chk]);
    uint32_t sB = smaddr(&Bh[0]);

    // ---- warp tiling: 4 warps 2x2, warp tile 32(M) x 64(N) ----
    int wid = tid >> 5, lane = tid & 31;
    int wm = (wid >> 1) * 32;
    int wn = (wid & 1) * 64;
    int r8 = lane >> 3, i8 = lane & 7;
    int a_frow = wm + (r8 & 1) * 8 + i8;       // + mt*16
    int a_fcol = (r8 >> 1) * 8;                // + kk*16
    int b_fkrow = (r8 & 1) * 8 + i8;           // + kk*16
    int b_fncol = wn + (r8 >> 1) * 8;          // + pair*16

    uint32_t sAf = smaddr(&Ah[a_frow * APITCH + a_fcol]);
    uint32_t sBf = smaddr(&Bh[b_fkrow * BPITCH + b_fncol]);

    float acc[2][8][4];
#pragma unroll
    for (int mt = 0; mt < 2; mt++)
#pragma unroll
        for (int nt = 0; nt < 8; nt++)
#pragma unroll
            for (int e = 0; e < 4; e++) acc[mt][nt][e] = 0.f;

    const int NSTEP = KPAD / BK;  // 8

    // prologue: stages 0..2
#pragma unroll
    for (int s = 0; s < 3; s++) {
        int k0 = s * BK;
        CP16(sA + s * (ASTG * 2),                 pWh + k0);
        CP16(sA + s * (ASTG * 2) + 32 * APITCH * 2, pWh + 32 * 256 + k0);
#pragma unroll
        for (int i = 0; i < 4; i++) {
            int e = tid + i * 128;
            int kr = e >> 4, nc = (e & 15) * 8;
            CP16(sB + s * (BSTG * 2) + (kr * BPITCH + nc) * 2,
                 pRh + (size_t)(k0 + kr) * NP + nc);
        }
        CP_COMMIT();
    }

#pragma unroll
    for (int s = 0; s < NSTEP; s++) {
        if (s <= NSTEP - 3) { CP_WAIT(2); }
        else if (s == NSTEP - 2) { CP_WAIT(1); }
        else { CP_WAIT(0); }
        __syncthreads();   // also proves step s-1 readers of buffer (s+3)&3 done

        if (s + 3 < NSTEP) {
            int k0 = (s + 3) * BK;
            int nb = (s + 3) & 3;
            CP16(sA + nb * (ASTG * 2),                 pWh + k0);
            CP16(sA + nb * (ASTG * 2) + 32 * APITCH * 2, pWh + 32 * 256 + k0);
#pragma unroll
            for (int i = 0; i < 4; i++) {
                int e = tid + i * 128;
                int kr = e >> 4, nc = (e & 15) * 8;
                CP16(sB + nb * (BSTG * 2) + (kr * BPITCH + nc) * 2,
                     pRh + (size_t)(k0 + kr) * NP + nc);
            }
            CP_COMMIT();
        }

        int buf = s & 3;
        uint32_t aBase = sAf + buf * (ASTG * 2);
        uint32_t bBase = sBf + buf * (BSTG * 2);

#pragma unroll
        for (int kk = 0; kk < 2; kk++) {
            // B fragments: 4 pairs of n16 -> 8 n8 tiles
            uint32_t bhf[8][2];
#pragma unroll
            for (int pair = 0; pair < 4; pair++) {
                uint32_t t4[4];
                ldsm4t(t4, bBase + kk * 16 * (BPITCH * 2) + pair * 32);
                bhf[pair * 2][0] = t4[0]; bhf[pair * 2][1] = t4[1];
                bhf[pair * 2 + 1][0] = t4[2]; bhf[pair * 2 + 1][1] = t4[3];
            }
#pragma unroll
            for (int mt = 0; mt < 2; mt++) {
                uint32_t ahf[4];
                ldsm4(ahf, aBase + mt * 16 * (APITCH * 2) + kk * 32);
#pragma unroll
                for (int nt = 0; nt < 8; nt++) {
                    mma16816(acc[mt][nt], ahf, bhf[nt]);
                }
            }
        }
    }

    // epilogue
#pragma unroll
    for (int mt = 0; mt < 2; mt++) {
#pragma unroll
        for (int nt = 0; nt < 8; nt++) {
            int l0 = bm + wm + mt * 16 + (lane >> 2);
            int n0 = bn + wn + nt * 8 + (lane & 3) * 2;
#pragma unroll
            for (int e = 0; e < 4; e++) {
                int l = l0 + (e >> 1) * 8;
                int n = n0 + (e & 1);
                if (l < L_LAYERS && n < NCOL) {
                    int t = n / N_THETA;
                    int a = n - t * N_THETA;
                    out[t * (L_LAYERS * N_THETA) + l * N_THETA + a] = acc[mt][nt][e];
                }
            }
        }
    }
}

extern "C" void kernel_launch(void* const* d_in, const int* in_sizes, int n_in,
                              void* d_out, int out_size) {
    const float* vp      = (const float*)d_in[0];
    const float* vs      = (const float*)d_in[1];
    const float* rho     = (const float*)d_in[2];
    const float* theta   = (const float*)d_in[3];
    const float* wavemat = (const float*)d_in[4];
    float* out = (float*)d_out;

    cudaFuncSetAttribute(zoe_gemm, cudaFuncAttributeMaxDynamicSharedMemorySize,
                         SMEM_BYTES);

    int nblk = (HTOTAL + WELEMS + 255) / 256;
    zoe_phase1<<<nblk, 256>>>(vp, vs, rho, theta, wavemat);

    dim3 grid((NCOL + BN - 1) / BN, 256 / BM);
    zoe_gemm<<<grid, 128, SMEM_BYTES>>>(out);
}